// round 17
// baseline (speedup 1.0000x reference)
#include <cuda_runtime.h>
#include <cuda_fp16.h>
#include <cstdint>

#define D_DIM 1024
#define H_DIM 512

#define BM 128
#define BN 128
#define BK 32
#define STAGES 3
#define THREADS 256
#define NCH (D_DIM / BK)   // 32 k-chunks

// halves per row: BK + 8 pad -> conflict-free frag LDS (bank = r*20+... distinct)
#define SAB_STRIDE 40
#define A_STAGE_HALVES (BM * SAB_STRIDE)   // 5120
#define B_STAGE_HALVES (BN * SAB_STRIDE)   // 5120
#define STAGE_HALVES (A_STAGE_HALVES + B_STAGE_HALVES)   // 10240 (20480 B)
#define EPI_FLOATS (H_DIM + H_DIM * 2)     // b1[512] + W2[1024]
#define SMEM_BYTES (STAGES * STAGE_HALVES * 2 + EPI_FLOATS * 4)   // 67584

__device__ __half g_W1Th[H_DIM * D_DIM];   // W1^T fp16, [H][D] (k-contig)

__device__ __forceinline__ unsigned h2_as_u32(__half2 h) {
    return *reinterpret_cast<unsigned*>(&h);
}

// f16-accumulate MMA: D(f16) = A(f16)*B(f16) + 0 ; promote outside
__device__ __forceinline__ void mma_f16_h(unsigned& d0, unsigned& d1,
                                          const unsigned* a,
                                          const unsigned* b) {
    asm volatile(
        "mma.sync.aligned.m16n8k16.row.col.f16.f16.f16.f16 "
        "{%0,%1}, {%2,%3,%4,%5}, {%6,%7}, {%8,%9};\n"
        : "=r"(d0), "=r"(d1)
        : "r"(a[0]), "r"(a[1]), "r"(a[2]), "r"(a[3]),
          "r"(b[0]), "r"(b[1]), "r"(0u), "r"(0u));
}

__device__ __forceinline__ void cp_async16(void* smem_dst, const void* gsrc) {
    uint32_t d = (uint32_t)__cvta_generic_to_shared(smem_dst);
    asm volatile("cp.async.cg.shared.global [%0], [%1], 16;" :: "r"(d),
                 "l"(gsrc) : "memory");
}

// ---- prep: W1 [D][H] fp32 -> W1^T [H][D] fp16 ----
__global__ void transpose_w1_kernel(const float* __restrict__ W1) {
    __shared__ float tile[32][33];
    int k0 = blockIdx.x * 32, n0 = blockIdx.y * 32;
    int tx = threadIdx.x, ty = threadIdx.y;   // (32, 8)
#pragma unroll
    for (int i = 0; i < 32; i += 8)
        tile[ty + i][tx] = W1[(size_t)(k0 + ty + i) * H_DIM + n0 + tx];
    __syncthreads();
#pragma unroll
    for (int i = 0; i < 32; i += 8)
        g_W1Th[(size_t)(n0 + ty + i) * D_DIM + k0 + tx] =
            __float2half_rn(tile[tx][ty + i]);
}

__global__ void init_patch_kernel(const float* __restrict__ b2,
                                  float* __restrict__ patch_logits, int total) {
    int i = blockIdx.x * blockDim.x + threadIdx.x;
    if (i < total) patch_logits[i] = b2[i & 1];
}

// ---- fused GEMM: patch_logits += relu(att*(X@W1) + b1) @ W2 ----
__global__ __launch_bounds__(THREADS, 2)
void gemm_fused_kernel(const float* __restrict__ features,
                       const float* __restrict__ attention,
                       const float* __restrict__ b1,
                       const float* __restrict__ W2,
                       float* __restrict__ patch_logits) {
    extern __shared__ __half smemh[];
    float* sEpi = (float*)(smemh + STAGES * STAGE_HALVES);

    const int tid = threadIdx.x;
    const int hblk = blockIdx.x;            // 0..3 (fast dim: L2 reuse of A)
    const int row0 = blockIdx.y * BM;
    const int h0 = hblk * BN;

    const int wid = tid >> 5;
    const int lane = tid & 31;
    const int gid = lane >> 2;              // 0..7
    const int tig = lane & 3;               // 0..3
    const int warp_m = (wid & 1) * 64;      // 0,64
    const int warp_n = (wid >> 1) * 32;     // 0,32,64,96

    for (int i = tid; i < H_DIM; i += THREADS) sEpi[i] = b1[i];
    for (int i = tid; i < H_DIM * 2; i += THREADS) sEpi[H_DIM + i] = W2[i];

    float attv[4][2];
#pragma unroll
    for (int mt = 0; mt < 4; mt++) {
        int r = row0 + warp_m + mt * 16 + gid;
        attv[mt][0] = __ldg(&attention[r]);
        attv[mt][1] = __ldg(&attention[r + 8]);
    }

    // A chunk: 128 rows x 32 fp32 -> fp16. Each thread: r=tid/2, 16 k-elements.
    const int ar = tid >> 1;
    const int aseg = (tid & 1) * 16;

    auto ldgA = [&](float4* a4, int kchunk) {
        const float* src =
            &features[(size_t)(row0 + ar) * D_DIM + kchunk * BK + aseg];
#pragma unroll
        for (int i = 0; i < 4; i++)
            a4[i] = *reinterpret_cast<const float4*>(src + i * 4);
    };
    auto stsA = [&](const float4* a4, int slot) {
        __half* dst = smemh + slot * STAGE_HALVES + ar * SAB_STRIDE + aseg;
        unsigned u[8];
#pragma unroll
        for (int i = 0; i < 4; i++) {
            u[i * 2 + 0] = h2_as_u32(__floats2half2_rn(a4[i].x, a4[i].y));
            u[i * 2 + 1] = h2_as_u32(__floats2half2_rn(a4[i].z, a4[i].w));
        }
        *reinterpret_cast<uint4*>(dst) = make_uint4(u[0], u[1], u[2], u[3]);
        *reinterpret_cast<uint4*>(dst + 8) = make_uint4(u[4], u[5], u[6], u[7]);
    };
    auto fillB = [&](int slot, int kchunk) {
        const int k0 = kchunk * BK;
        __half* sB = smemh + slot * STAGE_HALVES + A_STAGE_HALVES;
#pragma unroll
        for (int i = 0; i < 2; i++) {
            int idx = i * THREADS + tid;    // 0..511
            int n = idx >> 2;               // 0..127
            int c = idx & 3;                // 4 x 16B per row (32 halves)
            cp_async16(&sB[n * SAB_STRIDE + c * 8],
                       &g_W1Th[(size_t)(h0 + n) * D_DIM + k0 + c * 8]);
        }
        asm volatile("cp.async.commit_group;" ::: "memory");
    };

    float acc[4][4][4];
#pragma unroll
    for (int mt = 0; mt < 4; mt++)
#pragma unroll
        for (int nt = 0; nt < 4; nt++)
#pragma unroll
            for (int j = 0; j < 4; j++) acc[mt][nt][j] = 0.0f;

    // prologue: stages 0,1
    {
        float4 a4[4];
        fillB(0, 0);
        fillB(1, 1);
        ldgA(a4, 0);
        stsA(a4, 0);
        ldgA(a4, 1);
        stsA(a4, 1);
    }

    for (int ch = 0; ch < NCH; ch++) {
        if (ch == NCH - 1)
            asm volatile("cp.async.wait_group 0;" ::: "memory");
        else
            asm volatile("cp.async.wait_group 1;" ::: "memory");
        __syncthreads();

        float4 a4[4];
        const bool pre = (ch + 2 < NCH);
        if (pre) {
            ldgA(a4, ch + 2);            // issue early: latency hidden by compute
            fillB((ch + 2) % STAGES, ch + 2);
        }

        const __half* sA = smemh + (ch % STAGES) * STAGE_HALVES;
        const __half* sB = sA + A_STAGE_HALVES;

#pragma unroll
        for (int kb = 0; kb < BK; kb += 16) {
            unsigned afr[4][4];
#pragma unroll
            for (int mt = 0; mt < 4; mt++) {
                int r = warp_m + mt * 16 + gid;
                afr[mt][0] = *reinterpret_cast<const unsigned*>(
                    &sA[r * SAB_STRIDE + kb + 2 * tig]);
                afr[mt][1] = *reinterpret_cast<const unsigned*>(
                    &sA[(r + 8) * SAB_STRIDE + kb + 2 * tig]);
                afr[mt][2] = *reinterpret_cast<const unsigned*>(
                    &sA[r * SAB_STRIDE + kb + 2 * tig + 8]);
                afr[mt][3] = *reinterpret_cast<const unsigned*>(
                    &sA[(r + 8) * SAB_STRIDE + kb + 2 * tig + 8]);
            }
            unsigned bfr[4][2];
#pragma unroll
            for (int nt = 0; nt < 4; nt++) {
                int n = warp_n + nt * 8 + gid;
                bfr[nt][0] = *reinterpret_cast<const unsigned*>(
                    &sB[n * SAB_STRIDE + kb + 2 * tig]);
                bfr[nt][1] = *reinterpret_cast<const unsigned*>(
                    &sB[n * SAB_STRIDE + kb + 2 * tig + 8]);
            }
#pragma unroll
            for (int mt = 0; mt < 4; mt++)
#pragma unroll
                for (int nt = 0; nt < 4; nt++) {
                    unsigned d0, d1;
                    mma_f16_h(d0, d1, afr[mt], bfr[nt]);
                    float2 lo = __half22float2(*reinterpret_cast<__half2*>(&d0));
                    float2 hi = __half22float2(*reinterpret_cast<__half2*>(&d1));
                    acc[mt][nt][0] += lo.x;
                    acc[mt][nt][1] += lo.y;
                    acc[mt][nt][2] += hi.x;
                    acc[mt][nt][3] += hi.y;
                }
        }

        if (pre) stsA(a4, (ch + 2) % STAGES);
    }

    // ---- epilogue: att*acc + b1, ReLU, fold W2; quad-reduce; atomics ----
    const float* b1s = sEpi;
    const float* w2s = sEpi + H_DIM;
#pragma unroll
    for (int mt = 0; mt < 4; mt++) {
#pragma unroll
        for (int half = 0; half < 2; half++) {
            int r = row0 + warp_m + mt * 16 + gid + half * 8;
            float att = attv[mt][half];
            float pl0 = 0.0f, pl1 = 0.0f;
#pragma unroll
            for (int nt = 0; nt < 4; nt++) {
#pragma unroll
                for (int j = 0; j < 2; j++) {
                    int col = h0 + warp_n + nt * 8 + 2 * tig + j;
                    float v = fmaf(att, acc[mt][nt][half * 2 + j], b1s[col]);
                    v = fmaxf(v, 0.0f);
                    pl0 = fmaf(v, w2s[col * 2 + 0], pl0);
                    pl1 = fmaf(v, w2s[col * 2 + 1], pl1);
                }
            }
            pl0 += __shfl_xor_sync(0xFFFFFFFFu, pl0, 1);
            pl1 += __shfl_xor_sync(0xFFFFFFFFu, pl1, 1);
            pl0 += __shfl_xor_sync(0xFFFFFFFFu, pl0, 2);
            pl1 += __shfl_xor_sync(0xFFFFFFFFu, pl1, 2);
            if (tig == 0) {
                atomicAdd(&patch_logits[(size_t)r * 2 + 0], pl0);
                atomicAdd(&patch_logits[(size_t)r * 2 + 1], pl1);
            }
        }
    }
}

// ---- per-bag ragged segment sum ----
__global__ void bag_sum_kernel(const float* __restrict__ patch_logits,
                               const int* __restrict__ bag_sizes,
                               float* __restrict__ logits) {
    int b = blockIdx.x;
    int start = 0;
    for (int i = 0; i < b; i++) start += bag_sizes[i];
    int size = bag_sizes[b];

    float s0 = 0.0f, s1 = 0.0f;
    const float2* pl = reinterpret_cast<const float2*>(patch_logits);
    for (int i = threadIdx.x; i < size; i += blockDim.x) {
        float2 v = pl[start + i];
        s0 += v.x;
        s1 += v.y;
    }
#pragma unroll
    for (int off = 16; off > 0; off >>= 1) {
        s0 += __shfl_down_sync(0xFFFFFFFFu, s0, off);
        s1 += __shfl_down_sync(0xFFFFFFFFu, s1, off);
    }
    __shared__ float r0[8], r1[8];
    int w = threadIdx.x >> 5;
    if ((threadIdx.x & 31) == 0) { r0[w] = s0; r1[w] = s1; }
    __syncthreads();
    if (threadIdx.x == 0) {
        float t0 = 0.0f, t1 = 0.0f;
        int nw = blockDim.x >> 5;
        for (int i = 0; i < nw; i++) { t0 += r0[i]; t1 += r1[i]; }
        logits[b * 2 + 0] = t0;
        logits[b * 2 + 1] = t1;
    }
}

// ---- launch ----
extern "C" void kernel_launch(void* const* d_in, const int* in_sizes, int n_in,
                              void* d_out, int out_size) {
    const float* features  = (const float*)d_in[0];  // [N, D]
    const float* attention = (const float*)d_in[1];  // [N, 1]
    const int*   bag_sizes = (const int*)d_in[2];    // [B]
    const float* W1        = (const float*)d_in[3];  // [D, H]
    const float* b1        = (const float*)d_in[4];  // [H]
    const float* W2        = (const float*)d_in[5];  // [H, C]
    const float* b2        = (const float*)d_in[6];  // [C]

    const int N = in_sizes[1];
    const int B = in_sizes[2];

    float* logits = (float*)d_out;                  // [B, 2]
    float* patch_logits = logits + (size_t)B * 2;   // [N, 2]

    cudaFuncSetAttribute(gemm_fused_kernel,
                         cudaFuncAttributeMaxDynamicSharedMemorySize,
                         SMEM_BYTES);

    // 1) prep: W1 -> fp16 transposed scratch; patch_logits = b2 broadcast
    transpose_w1_kernel<<<dim3(D_DIM / 32, H_DIM / 32), dim3(32, 8)>>>(W1);
    init_patch_kernel<<<(N * 2 + 255) / 256, 256>>>(b2, patch_logits, N * 2);

    // 2) fused GEMM (f16-accumulate HMMA, fp32 promote per k16)
    dim3 grid(H_DIM / BN, N / BM);
    gemm_fused_kernel<<<grid, THREADS, SMEM_BYTES>>>(features, attention, b1,
                                                     W2, patch_logits);

    // 3) ragged per-bag segment sum
    bag_sum_kernel<<<B, 256>>>(patch_logits, bag_sizes, logits);
}